// round 1
// baseline (speedup 1.0000x reference)
#include <cuda_runtime.h>
#include <math.h>

#define N_NODES 4096
#define IN_F    512
#define NHEAD   8
#define DHEAD   64
#define CTOT    (NHEAD * DHEAD)   // 512

// Scratch (static device globals — no runtime allocation)
__device__ float g_mx[N_NODES * CTOT];     // mx, node-major: [n, h*64+d]  (8 MB, L2-resident)
__device__ float g_wexp[N_NODES * NHEAD];  // exp(mx[n,h,:] . a_dst[h])    (128 KB)

// ---------------------------------------------------------------------------
// Kernel 1: mx[n, h*64+d] = sum_f x[n,f] * W[h,f,d]
// Tiled fp32 GEMM, 128x128 block tile, BK=16, 256 threads, 8x8 per thread.
// Grid: (4096/128, 512/128) = (32, 4) = 128 blocks (one wave on 148 SMs).
// ---------------------------------------------------------------------------
#define BM 128
#define BN 128
#define BK 16

__global__ __launch_bounds__(256) void gemm_mx_kernel(
    const float* __restrict__ x, const float* __restrict__ W)
{
    __shared__ float As[BK][BM];   // A transposed: As[k][m]
    __shared__ float Bs[BK][BN];

    const int tid = threadIdx.x;
    const int tx  = tid & 15;      // 0..15 -> output cols
    const int ty  = tid >> 4;      // 0..15 -> output rows
    const int m0  = blockIdx.x * BM;
    const int c0  = blockIdx.y * BN;

    float acc[8][8];
    #pragma unroll
    for (int i = 0; i < 8; i++)
        #pragma unroll
        for (int j = 0; j < 8; j++) acc[i][j] = 0.f;

    for (int f0 = 0; f0 < IN_F; f0 += BK) {
        // --- load A tile: 128 rows x 16 f-cols (512 float4, 2 per thread) ---
        #pragma unroll
        for (int l = 0; l < 2; l++) {
            int idx = tid + l * 256;
            int row = idx >> 2;            // 0..127
            int fc  = (idx & 3) * 4;       // 0,4,8,12
            float4 v = *(const float4*)(x + (size_t)(m0 + row) * IN_F + f0 + fc);
            As[fc + 0][row] = v.x;
            As[fc + 1][row] = v.y;
            As[fc + 2][row] = v.z;
            As[fc + 3][row] = v.w;
        }
        // --- load B tile: 16 k-rows x 128 c-cols (512 float4, 2 per thread) ---
        // B[f, c] = W[(c>>6)*IN_F*DHEAD + f*DHEAD + (c&63)]
        #pragma unroll
        for (int l = 0; l < 2; l++) {
            int idx = tid + l * 256;
            int k   = idx >> 5;            // 0..15
            int cc  = (idx & 31) * 4;      // 0..124
            int c   = c0 + cc;
            const float* wp = W + (size_t)(c >> 6) * (IN_F * DHEAD)
                                + (size_t)(f0 + k) * DHEAD + (c & 63);
            *(float4*)&Bs[k][cc] = *(const float4*)wp;
        }
        __syncthreads();

        #pragma unroll
        for (int k = 0; k < BK; k++) {
            float a[8], b[8];
            *(float4*)(a)     = *(float4*)&As[k][ty * 8];
            *(float4*)(a + 4) = *(float4*)&As[k][ty * 8 + 4];
            *(float4*)(b)     = *(float4*)&Bs[k][tx * 8];
            *(float4*)(b + 4) = *(float4*)&Bs[k][tx * 8 + 4];
            #pragma unroll
            for (int i = 0; i < 8; i++)
                #pragma unroll
                for (int j = 0; j < 8; j++)
                    acc[i][j] += a[i] * b[j];
        }
        __syncthreads();
    }

    #pragma unroll
    for (int i = 0; i < 8; i++) {
        int n = m0 + ty * 8 + i;
        float* op = g_mx + (size_t)n * CTOT + c0 + tx * 8;
        *(float4*)(op)     = *(float4*)&acc[i][0];
        *(float4*)(op + 4) = *(float4*)&acc[i][4];
    }
}

// ---------------------------------------------------------------------------
// Kernel 2: g_wexp[n, h] = exp( mx[n, h*64 : h*64+64] . a_dst[h, :] )
// (source-term s_i cancels inside the row softmax, so only a_dst matters)
// One block per node, 8 warps = 8 heads, 2 elems per lane + shuffle reduce.
// ---------------------------------------------------------------------------
__global__ __launch_bounds__(256) void wexp_kernel(const float* __restrict__ a_dst)
{
    const int n    = blockIdx.x;
    const int h    = threadIdx.x >> 5;
    const int lane = threadIdx.x & 31;
    const float* mp = g_mx + (size_t)n * CTOT + h * DHEAD;
    const float* ap = a_dst + h * DHEAD;
    float t = mp[lane] * ap[lane] + mp[lane + 32] * ap[lane + 32];
    #pragma unroll
    for (int o = 16; o > 0; o >>= 1) t += __shfl_xor_sync(0xFFFFFFFFu, t, o);
    if (lane == 0) g_wexp[n * NHEAD + h] = __expf(t) * 0.0f + expf(t);
}

// ---------------------------------------------------------------------------
// Kernel 3: per row i:  out[i, h*64+d] = sum_{j: adj[i,j]>0} w[j,h] * mx[j, h*64+d]
//                                        / sum_j w[j,h]
// One block (512 threads) per row. Phase A: deterministic ordered neighbor
// compaction (16 warps x 256-col segments, ballot prefix). Phase B: gather.
// ---------------------------------------------------------------------------
__global__ __launch_bounds__(512) void aggregate_kernel(
    const float* __restrict__ adj, float* __restrict__ out)
{
    __shared__ unsigned short seg[16][256];
    __shared__ int cnts[16];

    const int i    = blockIdx.x;
    const int tid  = threadIdx.x;
    const int warp = tid >> 5;
    const int lane = tid & 31;

    // Phase A: each warp compacts nonzero columns of its 256-col slice, in order
    {
        const float* arow = adj + (size_t)i * N_NODES;
        int base = warp * 256;
        int cnt = 0;
        #pragma unroll
        for (int c8 = 0; c8 < 8; c8++) {
            int j = base + c8 * 32 + lane;
            float v = __ldg(arow + j);
            unsigned mask = __ballot_sync(0xFFFFFFFFu, v > 0.f);
            if (v > 0.f) {
                int pos = cnt + __popc(mask & ((1u << lane) - 1u));
                seg[warp][pos] = (unsigned short)j;
            }
            cnt += __popc(mask);
        }
        if (lane == 0) cnts[warp] = cnt;
    }
    __syncthreads();

    // Phase B: all 512 threads gather; thread t owns output channel t, head t/64
    const int h = tid >> 6;
    float acc = 0.f, den = 0.f;
    for (int w = 0; w < 16; w++) {
        int nw = cnts[w];
        const unsigned short* s = seg[w];
        int k = 0;
        // unrolled by 2 for load-level parallelism
        for (; k + 2 <= nw; k += 2) {
            int j0 = s[k], j1 = s[k + 1];
            float w0 = __ldg(g_wexp + j0 * NHEAD + h);
            float w1 = __ldg(g_wexp + j1 * NHEAD + h);
            float m0 = __ldg(g_mx + (size_t)j0 * CTOT + tid);
            float m1 = __ldg(g_mx + (size_t)j1 * CTOT + tid);
            acc += w0 * m0;
            acc += w1 * m1;
            den += w0 + w1;
        }
        if (k < nw) {
            int j0 = s[k];
            float w0 = __ldg(g_wexp + j0 * NHEAD + h);
            acc += w0 * __ldg(g_mx + (size_t)j0 * CTOT + tid);
            den += w0;
        }
    }
    out[(size_t)i * CTOT + tid] = acc / den;
}

// ---------------------------------------------------------------------------
// Inputs (metadata order): x[4096,512], adj[4096,4096], W[8,512,64],
//                          a_origin[8,64] (unused — cancels), a_dst[8,64]
// Output: float32 [4096, 512]
// ---------------------------------------------------------------------------
extern "C" void kernel_launch(void* const* d_in, const int* in_sizes, int n_in,
                              void* d_out, int out_size)
{
    const float* x     = (const float*)d_in[0];
    const float* adj   = (const float*)d_in[1];
    const float* W     = (const float*)d_in[2];
    const float* a_dst = (const float*)d_in[4];
    float* out = (float*)d_out;

    dim3 ggrid(N_NODES / BM, CTOT / BN);   // (32, 4)
    gemm_mx_kernel<<<ggrid, 256>>>(x, W);
    wexp_kernel<<<N_NODES, 256>>>(a_dst);
    aggregate_kernel<<<N_NODES, 512>>>(adj, out);
}